// round 11
// baseline (speedup 1.0000x reference)
#include <cuda_runtime.h>
#include <cstdint>

// DConv as implicit GEMM on mma.sync (tf32 m16n8k8) — tcgen05 unavailable
// (harness ptxas targets compute_103, no 'a' suffix).
// out[b,co,oy,ox] = sum_{ci,ky,kx} w[co,ci,ky,kx] * xs[b,ci,oy+ky,ox+kx]
// CTA tile: 256 px (16y x 16x), N=64 co, K=576 = 18 chunks of 32.
// A: 18x18 neighborhood resident in smem per tile (staged overlapping epilogue).
// B: all 18 chunks resident for the whole kernel.

__device__ __align__(256) float g_xpt[(size_t)16 * 162 * 162 * 64];
__device__ __align__(256) float g_wperm[18 * 2048];

__device__ __forceinline__ uint32_t smem_u32(const void* p) {
    uint32_t a;
    asm("{ .reg .u64 t; cvta.to.shared.u64 t, %1; cvt.u32.u64 %0, t; }" : "=r"(a) : "l"(p));
    return a;
}
__device__ __forceinline__ float tf32r(float v) {
    uint32_t b;
    asm("cvt.rna.tf32.f32 %0, %1;" : "=r"(b) : "f"(v));
    return __uint_as_float(b);
}
__device__ __forceinline__ void lds64(uint32_t& x, uint32_t& y, uint32_t addr) {
    asm volatile("ld.shared.v2.b32 {%0,%1}, [%2];" : "=r"(x), "=r"(y) : "r"(addr));
}
__device__ __forceinline__ void mma_tf32(float* d, const uint32_t* a,
                                         uint32_t b0, uint32_t b1) {
    asm volatile(
        "mma.sync.aligned.m16n8k8.row.col.f32.tf32.tf32.f32 "
        "{%0,%1,%2,%3}, {%4,%5,%6,%7}, {%8,%9}, {%0,%1,%2,%3};"
        : "+f"(d[0]), "+f"(d[1]), "+f"(d[2]), "+f"(d[3])
        : "r"(a[0]), "r"(a[1]), "r"(a[2]), "r"(a[3]), "r"(b0), "r"(b1));
}
#define CP_ASYNC16(dst, src) \
    asm volatile("cp.async.cg.shared.global [%0], [%1], 16;" :: "r"(dst), "l"(src))
#define CP_COMMIT() asm volatile("cp.async.commit_group;" ::: "memory")
#define CP_WAIT0()  asm volatile("cp.async.wait_group 0;" ::: "memory")

// ci position in the 64-float channels-last pixel vector: makes (c, c+4)
// adjacent so mma fragment pairs load as one LDS.64.
__device__ __forceinline__ int pos64(int ci) {
    int kk = ci & 31, t = kk >> 3, cc = kk & 7;
    return (ci & 32) + t * 8 + 2 * (cc & 3) + (cc >> 2);
}

// ---------------- prep_x: BW-bound rewrite ----------------
// One block per (i, b) row. ci outer loop: shift math uniform per iteration,
// threads j contiguous -> coalesced loads; smem transpose -> coalesced
// channels-last stores.
__global__ __launch_bounds__(256) void prep_x(const float* __restrict__ x) {
    __shared__ float tile[162 * 65];
    const int i = blockIdx.x, b = blockIdx.y;
    const int tid = threadIdx.x;
    const float* xb = x + (size_t)b * 64 * 25600;

    if (tid < 162) {
        const int j = tid;
#pragma unroll 1
        for (int ci = 0; ci < 64; ++ci) {
            const int cm = ci % 5;
            const int dy = (cm == 2) ? 1 : ((cm == 4) ? -1 : 0);
            const int dx = (cm == 1) ? 1 : ((cm == 3) ? -1 : 0);
            int p = i - dy;  if (p < 0) p += 162; else if (p >= 162) p -= 162;
            int q = j - dx;  if (q < 0) q += 162; else if (q >= 162) q -= 162;
            float v = 0.0f;
            if (p >= 1 && p <= 160 && q >= 1 && q <= 160)
                v = tf32r(xb[(size_t)ci * 25600 + (p - 1) * 160 + (q - 1)]);
            tile[j * 65 + pos64(ci)] = v;
        }
    }
    __syncthreads();
    const size_t base = (((size_t)b * 162 + i) * 162) * 64;
#pragma unroll 4
    for (int e = tid; e < 162 * 64; e += 256) {
        const int j = e >> 6, ci = e & 63;
        g_xpt[base + e] = tile[j * 65 + ci];
    }
}

// B image per chunk: 64 rows (co) x 128B (32 permuted tf32), 16B-slot swizzle by co&7.
__global__ void prep_w(const float* __restrict__ w) {
    int id = blockIdx.x * 256 + threadIdx.x;
    if (id >= 18 * 2048) return;
    int c = id >> 11, rr = id & 2047, co = rr >> 5, kk = rr & 31;
    int t = kk >> 3, cc = kk & 7;
    uint32_t off = (uint32_t)co * 128u + (uint32_t)(t * 8 + 2 * (cc & 3) + (cc >> 2)) * 4u;
    uint32_t swz = off ^ ((off >> 3) & 0x70u);
    int ci = (c & 1) * 32 + kk, s = c >> 1;
    g_wperm[c * 2048 + (swz >> 2)] = tf32r(w[((size_t)co * 64 + ci) * 9 + s]);
}

// ---------------- main MMA kernel ----------------
#define A_BYTES 82944                       // 18*18 px * 256B
#define SMEM_BYTES (A_BYTES + 18 * 8192)    // 230400

__device__ __forceinline__ void stage_A(uint32_t a_sb, int tid, int tile) {
    const int b = tile / 100, rr = tile % 100;
    const int y0 = (rr / 10) * 16, x0 = (rr % 10) * 16;
    const float* xt = g_xpt + (size_t)b * 26244 * 64;
#pragma unroll 1
    for (int e = tid; e < 5184; e += 256) {
        int p = e >> 4, s = e & 15;
        int row = p / 18, col = p - row * 18;
        const float* src = xt + ((size_t)(y0 + row) * 162 + (x0 + col)) * 64 + s * 4;
        CP_ASYNC16(a_sb + (uint32_t)p * 256u + (uint32_t)((s ^ (col & 7)) << 4), src);
    }
    CP_COMMIT();
}

__global__ __launch_bounds__(256, 1) void dconv_mma(float* __restrict__ out) {
    extern __shared__ char smem[];
    const uint32_t sb = smem_u32(smem);
    const uint32_t a_sb = sb;
    const uint32_t b_sb = sb + A_BYTES;
    const int tid = threadIdx.x;
    const int w = tid >> 5, l = tid & 31, q = l >> 2, r = l & 3;

    // Stage all B chunks once (already permuted + swizzled).
    for (int idx = tid; idx < 9216; idx += 256)
        CP_ASYNC16(b_sb + (uint32_t)idx * 16u, (const char*)g_wperm + (size_t)idx * 16);
    CP_COMMIT();
    // Prologue: stage first tile's A (overlaps with B arrival).
    if (blockIdx.x < 1600) stage_A(a_sb, tid, blockIdx.x);

    for (int tile = blockIdx.x; tile < 1600; tile += gridDim.x) {
        const int b  = tile / 100, rr = tile % 100;
        const int y0 = (rr / 10) * 16, x0 = (rr % 10) * 16;

        CP_WAIT0();
        __syncthreads();

        float acc[2][8][4];
#pragma unroll
        for (int i = 0; i < 2; ++i)
#pragma unroll
            for (int j = 0; j < 8; ++j)
#pragma unroll
                for (int k = 0; k < 4; ++k) acc[i][j][k] = 0.0f;

#pragma unroll 1
        for (int c = 0; c < 18; ++c) {
            const int s9 = c >> 1, h = c & 1;
            const int ky = (s9 >= 6) ? 2 : (s9 >= 3 ? 1 : 0);
            const int kx = s9 - ky * 3;
            const uint32_t bb = b_sb + (uint32_t)c * 8192u;
            const int xn0 = q + kx, xn1 = q + 8 + kx;
            const uint32_t rowb = (uint32_t)((2 * w + ky) * 18);
            const uint32_t p0 = a_sb + (rowb + (uint32_t)xn0) * 256u;
            const uint32_t p1 = a_sb + (rowb + (uint32_t)xn1) * 256u;
            const uint32_t k0 = (uint32_t)(xn0 & 7) << 4;
            const uint32_t k1 = (uint32_t)(xn1 & 7) << 4;
            const uint32_t bq = (uint32_t)q << 4;
            const uint32_t ob = (uint32_t)(h * 128 + 8 * r);
#pragma unroll
            for (int t = 0; t < 4; ++t) {
                const uint32_t off = ob + (uint32_t)(t * 32);
                uint32_t A0[4], A1[4];
                lds64(A0[0], A0[2], p0 + (off ^ k0));
                lds64(A0[1], A0[3], p1 + (off ^ k1));
                lds64(A1[0], A1[2], p0 + 4608u + (off ^ k0));   // yn+1 = +18*256
                lds64(A1[1], A1[3], p1 + 4608u + (off ^ k1));
#pragma unroll
                for (int nf = 0; nf < 8; ++nf) {
                    uint32_t b0, b1;
                    uint32_t boff = (uint32_t)((nf * 8 + q) * 128 + t * 32 + 8 * r);
                    lds64(b0, b1, bb + (boff ^ bq));
                    mma_tf32(acc[0][nf], A0, b0, b1);
                    mma_tf32(acc[1][nf], A1, b0, b1);
                }
            }
        }

        __syncthreads();                 // A fully consumed by all warps
        const int nxt = tile + gridDim.x;
        if (nxt < 1600) stage_A(a_sb, tid, nxt);   // overlaps epilogue stores

        // Epilogue: frag (mf,nf): row y0+2w+mf, x = x0+q / +8, co = nf*8+2r (+1).
#pragma unroll
        for (int mf = 0; mf < 2; ++mf) {
            const int y = y0 + 2 * w + mf;
#pragma unroll
            for (int nf = 0; nf < 8; ++nf) {
                const int co = nf * 8 + 2 * r;
                float* op = out + (((size_t)b * 64 + co) * 160 + y) * 160 + x0;
                op[q]             = acc[mf][nf][0];
                op[25600 + q]     = acc[mf][nf][1];
                op[q + 8]         = acc[mf][nf][2];
                op[25600 + q + 8] = acc[mf][nf][3];
            }
        }
    }
}

extern "C" void kernel_launch(void* const* d_in, const int* in_sizes, int n_in,
                              void* d_out, int out_size) {
    const float* x = (const float*)d_in[0];
    const float* w = (const float*)d_in[1];
    float* out = (float*)d_out;
    (void)in_sizes; (void)n_in; (void)out_size;

    prep_x<<<dim3(162, 16), 256>>>(x);
    prep_w<<<144, 256>>>(w);
    cudaFuncSetAttribute(dconv_mma, cudaFuncAttributeMaxDynamicSharedMemorySize, SMEM_BYTES);
    dconv_mma<<<148, 256, SMEM_BYTES>>>(out);
}

// round 12
// speedup vs baseline: 1.3049x; 1.3049x over previous
#include <cuda_runtime.h>
#include <cstdint>

// DConv as implicit GEMM on mma.sync (tf32 m16n8k8) — tcgen05 unavailable
// (harness ptxas targets compute_103, no 'a' suffix).
// out[b,co,oy,ox] = sum_{ci,ky,kx} w[co,ci,ky,kx] * xs[b,ci,oy+ky,ox+kx]
// CTA tile: 256 px (16y x 16x), N=64 co, K=576 = 18 chunks of 32.
// A: 18x18 neighborhood resident in smem per tile (staged overlapping epilogue).
// B: all 18 chunks resident for the whole kernel.

__device__ __align__(256) float g_xpt[(size_t)16 * 162 * 162 * 64];
__device__ __align__(256) float g_wperm[18 * 2048];

__device__ __forceinline__ uint32_t smem_u32(const void* p) {
    uint32_t a;
    asm("{ .reg .u64 t; cvta.to.shared.u64 t, %1; cvt.u32.u64 %0, t; }" : "=r"(a) : "l"(p));
    return a;
}
__device__ __forceinline__ float tf32r(float v) {
    uint32_t b;
    asm("cvt.rna.tf32.f32 %0, %1;" : "=r"(b) : "f"(v));
    return __uint_as_float(b);
}
__device__ __forceinline__ void lds64(uint32_t& x, uint32_t& y, uint32_t addr) {
    asm volatile("ld.shared.v2.b32 {%0,%1}, [%2];" : "=r"(x), "=r"(y) : "r"(addr));
}
__device__ __forceinline__ void mma_tf32(float* d, const uint32_t* a,
                                         uint32_t b0, uint32_t b1) {
    asm volatile(
        "mma.sync.aligned.m16n8k8.row.col.f32.tf32.tf32.f32 "
        "{%0,%1,%2,%3}, {%4,%5,%6,%7}, {%8,%9}, {%0,%1,%2,%3};"
        : "+f"(d[0]), "+f"(d[1]), "+f"(d[2]), "+f"(d[3])
        : "r"(a[0]), "r"(a[1]), "r"(a[2]), "r"(a[3]), "r"(b0), "r"(b1));
}
#define CP_ASYNC16(dst, src) \
    asm volatile("cp.async.cg.shared.global [%0], [%1], 16;" :: "r"(dst), "l"(src))
#define CP_COMMIT() asm volatile("cp.async.commit_group;" ::: "memory")
#define CP_WAIT0()  asm volatile("cp.async.wait_group 0;" ::: "memory")

// ci position in the 64-float channels-last pixel vector: makes (c, c+4)
// adjacent so mma fragment pairs load as one LDS.64.
__device__ __forceinline__ int pos64(int ci) {
    int kk = ci & 31, t = kk >> 3, cc = kk & 7;
    return (ci & 32) + t * 8 + 2 * (cc & 3) + (cc >> 2);
}

// ---------------- prep_x: bandwidth-bound ----------------
// Block = (27-col chunk, row i, batch b). All 256 threads, 7 independent
// iterations each; constant-divisor ci split; per-ci shift/permute packed in
// one smem table int. Coalesced loads (along j), contiguous 6912B store.
__global__ __launch_bounds__(256) void prep_x(const float* __restrict__ x) {
    __shared__ float tile[27 * 65];
    __shared__ int stab[64];
    const int j0 = blockIdx.x * 27, i = blockIdx.y, b = blockIdx.z;
    const int tid = threadIdx.x;

    if (tid < 64) {
        int cm = tid % 5;
        int dy = (cm == 2) ? 1 : ((cm == 4) ? -1 : 0);
        int dx = (cm == 1) ? 1 : ((cm == 3) ? -1 : 0);
        stab[tid] = (dy + 1) | ((dx + 1) << 2) | (pos64(tid) << 4);
    }
    __syncthreads();

    const float* xb = x + (size_t)b * 64 * 25600;
#pragma unroll
    for (int k = 0; k < 7; ++k) {
        int e = tid + k * 256;
        if (e < 1728) {
            int ci = (e * 607) >> 14;      // e/27 exact for e < 1728
            int jj = e - ci * 27;
            int tab = stab[ci];
            int p = i - ((tab & 3) - 1);
            int q = j0 + jj - (((tab >> 2) & 3) - 1);
            if (p < 0) p += 162; else if (p >= 162) p -= 162;
            if (q < 0) q += 162; else if (q >= 162) q -= 162;
            float v = 0.0f;
            if ((unsigned)(p - 1) < 160u && (unsigned)(q - 1) < 160u)
                v = tf32r(xb[(size_t)ci * 25600 + (p - 1) * 160 + (q - 1)]);
            tile[jj * 65 + (tab >> 4)] = v;
        }
    }
    __syncthreads();

    float* dst = g_xpt + (((size_t)b * 162 + i) * 162 + j0) * 64;
#pragma unroll
    for (int k = 0; k < 7; ++k) {
        int e = tid + k * 256;
        if (e < 1728) dst[e] = tile[(e >> 6) * 65 + (e & 63)];
    }
}

// B image per chunk: 64 rows (co) x 128B (32 permuted tf32), 16B-slot swizzle by co&7.
__global__ void prep_w(const float* __restrict__ w) {
    int id = blockIdx.x * 256 + threadIdx.x;
    if (id >= 18 * 2048) return;
    int c = id >> 11, rr = id & 2047, co = rr >> 5, kk = rr & 31;
    int t = kk >> 3, cc = kk & 7;
    uint32_t off = (uint32_t)co * 128u + (uint32_t)(t * 8 + 2 * (cc & 3) + (cc >> 2)) * 4u;
    uint32_t swz = off ^ ((off >> 3) & 0x70u);
    int ci = (c & 1) * 32 + kk, s = c >> 1;
    g_wperm[c * 2048 + (swz >> 2)] = tf32r(w[((size_t)co * 64 + ci) * 9 + s]);
}

// ---------------- main MMA kernel ----------------
#define A_BYTES 82944                       // 18*18 px * 256B
#define SMEM_BYTES (A_BYTES + 18 * 8192)    // 230400

__device__ __forceinline__ void stage_A(uint32_t a_sb, int tid, int tile) {
    const int b = tile / 100, rr = tile % 100;
    const int y0 = (rr / 10) * 16, x0 = (rr % 10) * 16;
    const float* xt = g_xpt + (size_t)b * 26244 * 64;
#pragma unroll 1
    for (int e = tid; e < 5184; e += 256) {
        int p = e >> 4, s = e & 15;
        int row = p / 18, col = p - row * 18;
        const float* src = xt + ((size_t)(y0 + row) * 162 + (x0 + col)) * 64 + s * 4;
        CP_ASYNC16(a_sb + (uint32_t)p * 256u + (uint32_t)((s ^ (col & 7)) << 4), src);
    }
    CP_COMMIT();
}

__global__ __launch_bounds__(256, 1) void dconv_mma(float* __restrict__ out) {
    extern __shared__ char smem[];
    const uint32_t sb = smem_u32(smem);
    const uint32_t a_sb = sb;
    const uint32_t b_sb = sb + A_BYTES;
    const int tid = threadIdx.x;
    const int w = tid >> 5, l = tid & 31, q = l >> 2, r = l & 3;

    // Stage all B chunks once (already permuted + swizzled).
    for (int idx = tid; idx < 9216; idx += 256)
        CP_ASYNC16(b_sb + (uint32_t)idx * 16u, (const char*)g_wperm + (size_t)idx * 16);
    CP_COMMIT();
    // Prologue: stage first tile's A (overlaps with B arrival).
    if (blockIdx.x < 1600) stage_A(a_sb, tid, blockIdx.x);

    for (int tile = blockIdx.x; tile < 1600; tile += gridDim.x) {
        const int b  = tile / 100, rr = tile % 100;
        const int y0 = (rr / 10) * 16, x0 = (rr % 10) * 16;

        CP_WAIT0();
        __syncthreads();

        float acc[2][8][4];
#pragma unroll
        for (int i = 0; i < 2; ++i)
#pragma unroll
            for (int j = 0; j < 8; ++j)
#pragma unroll
                for (int k = 0; k < 4; ++k) acc[i][j][k] = 0.0f;

#pragma unroll 1
        for (int c = 0; c < 18; ++c) {
            const int s9 = c >> 1, h = c & 1;
            const int ky = (s9 >= 6) ? 2 : (s9 >= 3 ? 1 : 0);
            const int kx = s9 - ky * 3;
            const uint32_t bb = b_sb + (uint32_t)c * 8192u;
            const int xn0 = q + kx, xn1 = q + 8 + kx;
            const uint32_t rowb = (uint32_t)((2 * w + ky) * 18);
            const uint32_t p0 = a_sb + (rowb + (uint32_t)xn0) * 256u;
            const uint32_t p1 = a_sb + (rowb + (uint32_t)xn1) * 256u;
            const uint32_t k0 = (uint32_t)(xn0 & 7) << 4;
            const uint32_t k1 = (uint32_t)(xn1 & 7) << 4;
            const uint32_t bq = (uint32_t)q << 4;
            const uint32_t ob = (uint32_t)(h * 128 + 8 * r);
#pragma unroll
            for (int t = 0; t < 4; ++t) {
                const uint32_t off = ob + (uint32_t)(t * 32);
                uint32_t A0[4], A1[4];
                lds64(A0[0], A0[2], p0 + (off ^ k0));
                lds64(A0[1], A0[3], p1 + (off ^ k1));
                lds64(A1[0], A1[2], p0 + 4608u + (off ^ k0));   // yn+1 = +18*256
                lds64(A1[1], A1[3], p1 + 4608u + (off ^ k1));
#pragma unroll
                for (int nf = 0; nf < 8; ++nf) {
                    uint32_t b0, b1;
                    uint32_t boff = (uint32_t)((nf * 8 + q) * 128 + t * 32 + 8 * r);
                    lds64(b0, b1, bb + (boff ^ bq));
                    mma_tf32(acc[0][nf], A0, b0, b1);
                    mma_tf32(acc[1][nf], A1, b0, b1);
                }
            }
        }

        __syncthreads();                 // A fully consumed by all warps
        const int nxt = tile + gridDim.x;
        if (nxt < 1600) stage_A(a_sb, tid, nxt);   // overlaps epilogue stores

        // Epilogue: frag (mf,nf): row y0+2w+mf, x = x0+q / +8, co = nf*8+2r (+1).
#pragma unroll
        for (int mf = 0; mf < 2; ++mf) {
            const int y = y0 + 2 * w + mf;
#pragma unroll
            for (int nf = 0; nf < 8; ++nf) {
                const int co = nf * 8 + 2 * r;
                float* op = out + (((size_t)b * 64 + co) * 160 + y) * 160 + x0;
                op[q]             = acc[mf][nf][0];
                op[25600 + q]     = acc[mf][nf][1];
                op[q + 8]         = acc[mf][nf][2];
                op[25600 + q + 8] = acc[mf][nf][3];
            }
        }
    }
}

extern "C" void kernel_launch(void* const* d_in, const int* in_sizes, int n_in,
                              void* d_out, int out_size) {
    const float* x = (const float*)d_in[0];
    const float* w = (const float*)d_in[1];
    float* out = (float*)d_out;
    (void)in_sizes; (void)n_in; (void)out_size;

    prep_x<<<dim3(6, 162, 16), 256>>>(x);
    prep_w<<<144, 256>>>(w);
    cudaFuncSetAttribute(dconv_mma, cudaFuncAttributeMaxDynamicSharedMemorySize, SMEM_BYTES);
    dconv_mma<<<148, 256, SMEM_BYTES>>>(out);
}